// round 1
// baseline (speedup 1.0000x reference)
#include <cuda_runtime.h>
#include <math.h>

// Problem constants (fixed by the dataset)
#define NGB 16          // graphs
#define NN  2048        // nodes per graph
#define NTT 32768       // total nodes
#define CIN 64
#define HID 128
#define KC  32
#define EDG 524288      // total edges
#define EPG 32768       // edges per graph
#define GN_EPS 1e-5f
#define SELU_SCALE 1.0507009873554805f
#define SELU_ALPHA 1.6732632423543772f

// ---------------- scratch (device globals; no allocation allowed) ----------------
__device__ __align__(16) float g_sum[NGB * CIN];
__device__ __align__(16) float g_sumsq[NGB * CIN];
__device__ __align__(16) float g_degi[NTT];            // in-degree (no self loop yet)
__device__ __align__(16) float g_dego[NTT];            // out-degree (adj degrees)
__device__ __align__(16) float g_dinv[NTT];
__device__ __align__(16) float g_hw[NTT * HID];        // (graphnorm(x)) @ w1
__device__ __align__(16) float g_agg[NTT * HID];       // GCN aggregation
__device__ __align__(16) float g_xd[NTT * HID];        // selu(agg+b1)
__device__ __align__(16) float g_s[NTT * KC];          // aligned copy of s
__device__ __align__(16) float g_tr[NGB];              // trace(out_adj)
__device__ __align__(16) float g_ca[NGB * KC];
__device__ __align__(16) float g_cs[NGB * KC];
__device__ __align__(16) float g_ss[NGB * KC * KC];
__device__ __align__(16) float g_outacc[NGB * KC * HID];

__device__ __forceinline__ float selu_f(float v) {
    return v > 0.f ? SELU_SCALE * v : SELU_SCALE * SELU_ALPHA * (expf(v) - 1.f);
}

// ---------------- kernels ----------------

__global__ void zero_k() {
    int i = blockIdx.x * blockDim.x + threadIdx.x;
    int stride = gridDim.x * blockDim.x;
    for (int j = i; j < NTT; j += stride) { g_degi[j] = 0.f; g_dego[j] = 0.f; }
    for (int j = i; j < NGB * KC * HID; j += stride) g_outacc[j] = 0.f;
    for (int j = i; j < NGB * KC * KC; j += stride) g_ss[j] = 0.f;
    for (int j = i; j < NGB * CIN; j += stride) { g_sum[j] = 0.f; g_sumsq[j] = 0.f; }
    for (int j = i; j < NGB * KC; j += stride) { g_ca[j] = 0.f; g_cs[j] = 0.f; }
    for (int j = i; j < NGB; j += stride) g_tr[j] = 0.f;
}

// per-graph sum & sumsq per channel. grid = NGB*8 blocks of 512.
__global__ void __launch_bounds__(512) gn_stats_k(const float* __restrict__ x) {
    int g = blockIdx.x >> 3;
    int part = blockIdx.x & 7;           // 256 rows per part
    int t = threadIdx.x;
    int c = t & 63, rp = t >> 6;         // 8 row-phases
    float s = 0.f, q = 0.f;
    const float* xb = x + (size_t)g * NN * CIN;
    int r0 = part * 256;
    for (int r = r0 + rp; r < r0 + 256; r += 8) {
        float v = xb[r * CIN + c];
        s += v; q += v * v;
    }
    __shared__ float sh[2][8][64];
    sh[0][rp][c] = s; sh[1][rp][c] = q;
    __syncthreads();
    if (t < 64) {
        float ss = 0.f, qq = 0.f;
#pragma unroll
        for (int i = 0; i < 8; i++) { ss += sh[0][i][t]; qq += sh[1][i][t]; }
        atomicAdd(&g_sum[g * 64 + t], ss);
        atomicAdd(&g_sumsq[g * 64 + t], qq);
    }
}

__global__ void deg_hist_k(const int* __restrict__ ei) {
    int e = blockIdx.x * blockDim.x + threadIdx.x;
    if (e < EDG) {
        atomicAdd(&g_degi[ei[EDG + e]], 1.f);   // dst in-degree
        atomicAdd(&g_dego[ei[e]], 1.f);         // src out-degree (adj degrees)
    }
}

__global__ void dinv_k() {
    int i = blockIdx.x * blockDim.x + threadIdx.x;
    if (i < NTT) g_dinv[i] = rsqrtf(g_degi[i] + 1.f);   // +1 self loop
}

// fused GraphNorm + GEMM1: hw = graphnorm(x) @ w1.  grid 2048 blocks, 128 threads, 16 rows/block
__global__ void __launch_bounds__(128) gn_gemm1_k(
    const float* __restrict__ x, const float* __restrict__ gw,
    const float* __restrict__ gb, const float* __restrict__ gms,
    const float* __restrict__ w1)
{
    __shared__ float w1s[CIN * HID];   // 32 KB
    __shared__ float A[CIN], S[CIN], Bc[CIN];
    __shared__ float hsh[2][CIN];
    int t = threadIdx.x;
    int row0 = blockIdx.x * 16;
    int g = row0 / NN;
    for (int i = t; i < CIN * HID; i += 128) w1s[i] = w1[i];
    if (t < 64) {
        float mean = g_sum[g * 64 + t] * (1.f / NN);
        float alpha = gms[t];
        float var = g_sumsq[g * 64 + t] * (1.f / NN) - (2.f * alpha - alpha * alpha) * mean * mean;
        S[t] = gw[t] * rsqrtf(var + GN_EPS);
        A[t] = alpha * mean;
        Bc[t] = gb[t];
    }
    __syncthreads();
    int rr = t >> 6, c = t & 63;
    for (int p = 0; p < 8; p++) {
        int r = row0 + 2 * p;
        float v = x[(size_t)(r + rr) * CIN + c];
        hsh[rr][c] = (v - A[c]) * S[c] + Bc[c];
        __syncthreads();
        float a0 = 0.f, a1 = 0.f;
#pragma unroll
        for (int c2 = 0; c2 < CIN; c2++) {
            float w = w1s[c2 * HID + t];
            a0 += hsh[0][c2] * w;
            a1 += hsh[1][c2] * w;
        }
        g_hw[(size_t)r * HID + t] = a0;
        g_hw[(size_t)(r + 1) * HID + t] = a1;
        __syncthreads();
    }
}

// agg[i] = dinv[i]^2 * hw[i]  (self loop contribution)
__global__ void agg_init_k() {
    int i = blockIdx.x * blockDim.x + threadIdx.x;   // float4 index, total NTT*32
    if (i < NTT * 32) {
        int row = i >> 5;
        float d = g_dinv[row];
        float w = d * d;
        float4 v = ((const float4*)g_hw)[i];
        v.x *= w; v.y *= w; v.z *= w; v.w *= w;
        ((float4*)g_agg)[i] = v;
    }
}

// edge scatter: agg[dst] += dinv[src]*dinv[dst]*hw[src].  warp per edge, lane = 4 channels
__global__ void __launch_bounds__(256) edge_agg_k(const int* __restrict__ ei) {
    int e = blockIdx.x * 8 + (threadIdx.x >> 5);
    int l = threadIdx.x & 31;
    int src = ei[e], dst = ei[EDG + e];
    float w = g_dinv[src] * g_dinv[dst];
    float4 v = ((const float4*)g_hw)[src * 32 + l];
    float* a = g_agg + (size_t)dst * HID + l * 4;
    atomicAdd(a + 0, v.x * w);
    atomicAdd(a + 1, v.y * w);
    atomicAdd(a + 2, v.z * w);
    atomicAdd(a + 3, v.w * w);
}

// xd = selu(agg + b1); s = softmax(xd @ w2 + b2).  warp per row.
__global__ void __launch_bounds__(256) xd_softmax_k(
    const float* __restrict__ b1, const float* __restrict__ w2,
    const float* __restrict__ b2, float* __restrict__ s_out)
{
    __shared__ float w2s[HID * KC];   // 16 KB
    __shared__ float xds[8][HID];
    int t = threadIdx.x, wp = t >> 5, l = t & 31;
    for (int i = t; i < HID * KC; i += 256) w2s[i] = w2[i];
    __syncthreads();
    float4 bv = ((const float4*)b1)[l];
    float bz = b2[l];
    int warps_total = gridDim.x * 8;
    for (int row = blockIdx.x * 8 + wp; row < NTT; row += warps_total) {
        float4 av = ((const float4*)g_agg)[row * 32 + l];
        float4 xv;
        xv.x = selu_f(av.x + bv.x);
        xv.y = selu_f(av.y + bv.y);
        xv.z = selu_f(av.z + bv.z);
        xv.w = selu_f(av.w + bv.w);
        ((float4*)g_xd)[row * 32 + l] = xv;
        *((float4*)&xds[wp][l * 4]) = xv;
        __syncwarp();
        float z = bz;
#pragma unroll
        for (int j = 0; j < HID; j++) z += xds[wp][j] * w2s[j * KC + l];
        float mx = z;
#pragma unroll
        for (int o = 16; o; o >>= 1) mx = fmaxf(mx, __shfl_xor_sync(0xffffffffu, mx, o));
        float ez = expf(z - mx);
        float sm = ez;
#pragma unroll
        for (int o = 16; o; o >>= 1) sm += __shfl_xor_sync(0xffffffffu, sm, o);
        float sv = ez / sm;
        s_out[(size_t)row * KC + l] = sv;
        g_s[(size_t)row * KC + l] = sv;
        __syncwarp();
    }
}

// per-graph reductions: out = s^T xd, ss = s^T s, ca = s^T deg, cs = s^T 1
// grid = 16 graphs * 16 chunks (128 nodes each), 512 threads
__global__ void __launch_bounds__(512) pool_k() {
    int g = blockIdx.x >> 4;
    int chunk = blockIdx.x & 15;
    int node0 = g * NN + chunk * 128;
    __shared__ float ssh[128 * 32];   // 16 KB
    __shared__ float dsh[128];
    int t = threadIdx.x;
    for (int i = t; i < 128 * 32; i += 512) ssh[i] = g_s[(size_t)node0 * 32 + i];
    if (t < 128) dsh[t] = g_dego[node0 + t];
    __syncthreads();

    int f = t & 127, kb = t >> 7;      // kb in 0..3
    int k1a = t >> 5;                  // 0..15
    int k2 = t & 31;
    float acc[8];
#pragma unroll
    for (int j = 0; j < 8; j++) acc[j] = 0.f;
    float ss0 = 0.f, ss1 = 0.f, csacc = 0.f, caacc = 0.f;

    for (int n = 0; n < 128; n++) {
        float xv = g_xd[(size_t)(node0 + n) * HID + f];
        const float* srow = &ssh[n * 32];
#pragma unroll
        for (int j = 0; j < 8; j++) acc[j] += srow[kb + 4 * j] * xv;
        float sv2 = srow[k2];
        ss0 += srow[k1a] * sv2;
        ss1 += srow[k1a + 16] * sv2;
        if (t < 32) { float sv = srow[t]; csacc += sv; caacc += sv * dsh[n]; }
    }

    float* oa = g_outacc + (size_t)g * KC * HID;
#pragma unroll
    for (int j = 0; j < 8; j++) atomicAdd(&oa[(kb + 4 * j) * HID + f], acc[j]);
    atomicAdd(&g_ss[g * 1024 + t], ss0);          // cell t: (t>>5, t&31)
    atomicAdd(&g_ss[g * 1024 + t + 512], ss1);
    if (t < 32) {
        atomicAdd(&g_cs[g * 32 + t], csacc);
        atomicAdd(&g_ca[g * 32 + t], caacc);
    }
}

// trace(out_adj)[b] = sum over edges of dot(s[src], s[dst])
__global__ void __launch_bounds__(256) trace_k(const int* __restrict__ ei) {
    __shared__ float red[256];
    int base = blockIdx.x * 512;   // 512 edges per block; graph-aligned (EPG=32768)
    float accum = 0.f;
    const float4* s4 = (const float4*)g_s;
#pragma unroll
    for (int i = 0; i < 2; i++) {
        int e = base + i * 256 + threadIdx.x;
        int src = ei[e], dst = ei[EDG + e];
        float d = 0.f;
#pragma unroll
        for (int j = 0; j < 8; j++) {
            float4 a = s4[src * 8 + j], b = s4[dst * 8 + j];
            d += a.x * b.x + a.y * b.y + a.z * b.z + a.w * b.w;
        }
        accum += d;
    }
    red[threadIdx.x] = accum;
    __syncthreads();
    for (int o = 128; o; o >>= 1) {
        if (threadIdx.x < o) red[threadIdx.x] += red[threadIdx.x + o];
        __syncthreads();
    }
    if (threadIdx.x == 0) atomicAdd(&g_tr[base / EPG], red[0]);
}

// log_softmax(selu(outacc)) over F=128.  grid 512 (b,k) rows, 128 threads.
__global__ void __launch_bounds__(128) out_final_k(float* __restrict__ outp) {
    int r = blockIdx.x;
    int t = threadIdx.x;
    __shared__ float shm[4], shs[4];
    float y = selu_f(g_outacc[(size_t)r * HID + t]);
    float mx = y;
#pragma unroll
    for (int o = 16; o; o >>= 1) mx = fmaxf(mx, __shfl_xor_sync(0xffffffffu, mx, o));
    if ((t & 31) == 0) shm[t >> 5] = mx;
    __syncthreads();
    float mall = fmaxf(fmaxf(shm[0], shm[1]), fmaxf(shm[2], shm[3]));
    float e = expf(y - mall);
    float sm = e;
#pragma unroll
    for (int o = 16; o; o >>= 1) sm += __shfl_xor_sync(0xffffffffu, sm, o);
    if ((t & 31) == 0) shs[t >> 5] = sm;
    __syncthreads();
    float tot = shs[0] + shs[1] + shs[2] + shs[3];
    outp[(size_t)r * HID + t] = y - mall - logf(tot);
}

// scalar loss.  1 block, 16 warps (warp per graph).
__global__ void __launch_bounds__(512) loss_k(float* __restrict__ outp) {
    int w = threadIdx.x >> 5, l = threadIdx.x & 31;
    __shared__ float parts[16];
    // m = 0.5 * sum(out-degrees)
    float dsum = 0.f;
    for (int n = l; n < NN; n += 32) dsum += g_dego[w * NN + n];
#pragma unroll
    for (int o = 16; o; o >>= 1) dsum += __shfl_xor_sync(0xffffffffu, dsum, o);
    float m = 0.5f * dsum;

    // spectral
    float ca = g_ca[w * 32 + l];
    float cn = ca * ca;
#pragma unroll
    for (int o = 16; o; o >>= 1) cn += __shfl_xor_sync(0xffffffffu, cn, o);
    float norm_tr = cn / (2.f * m);
    float spec = -(g_tr[w] - norm_tr) / (2.f * m);

    // ortho: sqrt(2 - 2*tr(ss)/(||ss||_F * sqrt(K)))
    float sq = 0.f;
    for (int i = l; i < KC * KC; i += 32) { float v = g_ss[w * 1024 + i]; sq += v * v; }
#pragma unroll
    for (int o = 16; o; o >>= 1) sq += __shfl_xor_sync(0xffffffffu, sq, o);
    float fro = sqrtf(sq);
    float dtr = g_ss[w * 1024 + l * 33];   // diag element l
#pragma unroll
    for (int o = 16; o; o >>= 1) dtr += __shfl_xor_sync(0xffffffffu, dtr, o);
    float ortho = sqrtf(fmaxf(2.f - 2.f * dtr / (fro * sqrtf((float)KC)), 0.f));

    // cluster
    float cs = g_cs[w * 32 + l];
    float csn = cs * cs;
#pragma unroll
    for (int o = 16; o; o >>= 1) csn += __shfl_xor_sync(0xffffffffu, csn, o);
    float clus = sqrtf(csn) / (float)NN * sqrtf((float)KC) - 1.f;

    if (l == 0) parts[w] = spec + ortho + clus;
    __syncthreads();
    if (threadIdx.x == 0) {
        float tot = 0.f;
#pragma unroll
        for (int i = 0; i < 16; i++) tot += parts[i];
        outp[NGB * KC * HID] = tot / (float)NGB;   // outp[65536]
    }
}

// ---------------- launch ----------------
extern "C" void kernel_launch(void* const* d_in, const int* in_sizes, int n_in,
                              void* d_out, int out_size) {
    const float *x = 0, *gw = 0, *gb = 0, *gms = 0, *w1 = 0, *b1 = 0, *w2 = 0, *b2 = 0;
    const int *ei = 0;
    int n64 = 0;
    for (int i = 0; i < n_in; i++) {
        int sz = in_sizes[i];
        if (sz == NTT * CIN)       x = (const float*)d_in[i];
        else if (sz == 2 * EDG)    ei = (const int*)d_in[i];
        else if (sz == NTT)        { /* batch, unused (uniform graphs) */ }
        else if (sz == CIN) {
            if (n64 == 0) gw = (const float*)d_in[i];
            else if (n64 == 1) gb = (const float*)d_in[i];
            else gms = (const float*)d_in[i];
            n64++;
        }
        else if (sz == CIN * HID)  w1 = (const float*)d_in[i];
        else if (sz == HID)        b1 = (const float*)d_in[i];
        else if (sz == HID * KC)   w2 = (const float*)d_in[i];
        else if (sz == KC)         b2 = (const float*)d_in[i];
    }
    float* outp = (float*)d_out;
    float* s_out = outp + NGB * KC * HID + 1;   // s at offset 65537

    zero_k<<<256, 256>>>();
    gn_stats_k<<<NGB * 8, 512>>>(x);
    deg_hist_k<<<EDG / 256, 256>>>(ei);
    dinv_k<<<NTT / 256, 256>>>();
    gn_gemm1_k<<<NTT / 16, 128>>>(x, gw, gb, gms, w1);
    agg_init_k<<<(NTT * 32) / 512, 512>>>();
    edge_agg_k<<<EDG / 8, 256>>>(ei);
    xd_softmax_k<<<128, 256>>>(b1, w2, b2, s_out);
    pool_k<<<NGB * 16, 512>>>();
    trace_k<<<EDG / 512, 256>>>(ei);
    out_final_k<<<NGB * KC, 128>>>(outp);
    loss_k<<<1, 512>>>(outp);
}

// round 2
// speedup vs baseline: 1.4327x; 1.4327x over previous
#include <cuda_runtime.h>
#include <math.h>

// Problem constants (fixed by the dataset)
#define NGB 16          // graphs
#define NN  2048        // nodes per graph
#define NTT 32768       // total nodes
#define CIN 64
#define HID 128
#define KC  32
#define EDG 524288      // total edges
#define EPG 32768       // edges per graph
#define GN_EPS 1e-5f
#define SELU_SCALE 1.0507009873554805f
#define SELU_ALPHA 1.6732632423543772f

// ---------------- scratch (device globals; no allocation allowed) ----------------
__device__ __align__(16) float g_sum[NGB * CIN];
__device__ __align__(16) float g_sumsq[NGB * CIN];
__device__ int   g_indeg[NTT];                 // in-degree (excl self loop)
__device__ int   g_odeg[NTT];                  // out-degree (adj degrees)
__device__ int   g_rowptr[NTT];                // CSR row start (by dst)
__device__ int   g_cursor[NTT];                // scatter cursors
__device__ int   g_csrsrc[EDG];                // CSR: src node per slot
__device__ __align__(16) float g_dinv[NTT];
__device__ __align__(16) float g_hw[NTT * HID];   // dinv * (graphnorm(x) @ w1)
__device__ __align__(16) float g_xd[NTT * HID];   // selu(agg+b1)
__device__ __align__(16) float g_s[NTT * KC];     // aligned copy of s
__device__ float g_tr[NGB];                       // trace(out_adj)
__device__ float g_ca[NGB * KC];
__device__ float g_cs[NGB * KC];
__device__ __align__(16) float g_ss[NGB * KC * KC];
__device__ __align__(16) float g_outacc[NGB * KC * HID];

__device__ __forceinline__ float selu_f(float v) {
    return v > 0.f ? SELU_SCALE * v : SELU_SCALE * SELU_ALPHA * (expf(v) - 1.f);
}

// ---------------- kernels ----------------

__global__ void zero_k() {
    int i = blockIdx.x * blockDim.x + threadIdx.x;
    int stride = gridDim.x * blockDim.x;
    for (int j = i; j < NTT; j += stride) { g_indeg[j] = 0; g_odeg[j] = 0; }
    for (int j = i; j < NGB * KC * HID; j += stride) g_outacc[j] = 0.f;
    for (int j = i; j < NGB * KC * KC; j += stride) g_ss[j] = 0.f;
    for (int j = i; j < NGB * CIN; j += stride) { g_sum[j] = 0.f; g_sumsq[j] = 0.f; }
    for (int j = i; j < NGB * KC; j += stride) { g_ca[j] = 0.f; g_cs[j] = 0.f; }
    for (int j = i; j < NGB; j += stride) g_tr[j] = 0.f;
}

// per-graph sum & sumsq per channel. grid = NGB*8 blocks of 512.
__global__ void __launch_bounds__(512) gn_stats_k(const float* __restrict__ x) {
    int g = blockIdx.x >> 3;
    int part = blockIdx.x & 7;           // 256 rows per part
    int t = threadIdx.x;
    int c = t & 63, rp = t >> 6;         // 8 row-phases
    float s = 0.f, q = 0.f;
    const float* xb = x + (size_t)g * NN * CIN;
    int r0 = part * 256;
    for (int r = r0 + rp; r < r0 + 256; r += 8) {
        float v = xb[r * CIN + c];
        s += v; q += v * v;
    }
    __shared__ float sh[2][8][64];
    sh[0][rp][c] = s; sh[1][rp][c] = q;
    __syncthreads();
    if (t < 64) {
        float ss = 0.f, qq = 0.f;
#pragma unroll
        for (int i = 0; i < 8; i++) { ss += sh[0][i][t]; qq += sh[1][i][t]; }
        atomicAdd(&g_sum[g * 64 + t], ss);
        atomicAdd(&g_sumsq[g * 64 + t], qq);
    }
}

__global__ void deg_hist_k(const int* __restrict__ ei) {
    int e = blockIdx.x * blockDim.x + threadIdx.x;
    if (e < EDG) {
        atomicAdd(&g_indeg[ei[EDG + e]], 1);   // dst in-degree
        atomicAdd(&g_odeg[ei[e]], 1);          // src out-degree (adj degrees)
    }
}

// exclusive prefix sum over in-degrees -> rowptr/cursor; also dinv. 1 block of 1024.
__global__ void __launch_bounds__(1024) scan_k() {
    int t = threadIdx.x;
    int base = t * 32;
    int loc[32];
    int s = 0;
#pragma unroll
    for (int i = 0; i < 32; i++) { loc[i] = g_indeg[base + i]; s += loc[i]; }
    __shared__ int sh[1024];
    sh[t] = s;
    __syncthreads();
    for (int off = 1; off < 1024; off <<= 1) {
        int v = (t >= off) ? sh[t - off] : 0;
        __syncthreads();
        sh[t] += v;
        __syncthreads();
    }
    int run = sh[t] - s;       // exclusive prefix
#pragma unroll
    for (int i = 0; i < 32; i++) {
        g_rowptr[base + i] = run;
        g_cursor[base + i] = run;
        g_dinv[base + i] = rsqrtf((float)loc[i] + 1.f);   // +1 self loop
        run += loc[i];
    }
}

// CSR scatter: slot = cursor[dst]++, csrsrc[slot] = src
__global__ void csr_scatter_k(const int* __restrict__ ei) {
    int e = blockIdx.x * blockDim.x + threadIdx.x;
    if (e < EDG) {
        int src = ei[e], dst = ei[EDG + e];
        int pos = atomicAdd(&g_cursor[dst], 1);
        g_csrsrc[pos] = src;
    }
}

// fused GraphNorm + GEMM1 (+ dinv scaling): g_hw = dinv * (graphnorm(x) @ w1)
// grid 2048 blocks of 128 threads, 16 rows/block, transposed-w1 shared layout.
__global__ void __launch_bounds__(128) gn_gemm1_k(
    const float* __restrict__ x, const float* __restrict__ gw,
    const float* __restrict__ gb, const float* __restrict__ gms,
    const float* __restrict__ w1)
{
    __shared__ float w1t[HID * (CIN + 4)];   // ~34 KB, w1t[t][c] = w1[c][t]
    __shared__ float A[CIN], S[CIN], Bc[CIN];
    __shared__ float hsh[8][CIN];
    __shared__ float dvs[16];
    int t = threadIdx.x;
    int row0 = blockIdx.x * 16;
    int g = row0 / NN;
    for (int c = 0; c < CIN; c++)
        w1t[t * (CIN + 4) + c] = w1[c * HID + t];
    if (t < CIN) {
        float mean = g_sum[g * 64 + t] * (1.f / NN);
        float alpha = gms[t];
        float var = g_sumsq[g * 64 + t] * (1.f / NN) - (2.f * alpha - alpha * alpha) * mean * mean;
        S[t] = gw[t] * rsqrtf(var + GN_EPS);
        A[t] = alpha * mean;
        Bc[t] = gb[t];
    }
    if (t < 16) dvs[t] = g_dinv[row0 + t];
    __syncthreads();
    for (int p = 0; p < 2; p++) {
        int r0 = row0 + p * 8;
#pragma unroll
        for (int i = 0; i < 4; i++) {
            int idx = t + i * 128;
            int rr = idx >> 6, c = idx & 63;
            float v = x[(size_t)(r0 + rr) * CIN + c];
            hsh[rr][c] = (v - A[c]) * S[c] + Bc[c];
        }
        __syncthreads();
        float acc[8];
#pragma unroll
        for (int r = 0; r < 8; r++) acc[r] = 0.f;
#pragma unroll
        for (int c = 0; c < CIN; c += 4) {
            float4 w = *(const float4*)&w1t[t * (CIN + 4) + c];
#pragma unroll
            for (int r = 0; r < 8; r++) {
                float4 h = *(const float4*)&hsh[r][c];
                acc[r] += w.x * h.x + w.y * h.y + w.z * h.z + w.w * h.w;
            }
        }
#pragma unroll
        for (int r = 0; r < 8; r++)
            g_hw[(size_t)(r0 + r) * HID + t] = acc[r] * dvs[p * 8 + r];
        __syncthreads();
    }
}

// fused CSR gather + SELU + softmax(xd @ w2 + b2).
// one warp per dst row; 4096 blocks x 256 threads = 32768 warps.
__global__ void __launch_bounds__(256) gxs_k(
    const float* __restrict__ b1, const float* __restrict__ w2,
    const float* __restrict__ b2, float* __restrict__ s_out)
{
    __shared__ float w2t[KC * (HID + 4)];   // ~17 KB, w2t[l][j] = w2[j][l]
    __shared__ float xds[8][HID];
    int t = threadIdx.x, wp = t >> 5, l = t & 31;
    for (int idx = t; idx < KC * HID; idx += 256) {
        int j = idx >> 5, ll = idx & 31;
        w2t[ll * (HID + 4) + j] = w2[idx];
    }
    __syncthreads();

    int row = blockIdx.x * 8 + wp;
    const float4* hw4 = (const float4*)g_hw;
    float dd = g_dinv[row];
    float4 acc = hw4[(size_t)row * 32 + l];      // self-loop term p_d
    int start = g_rowptr[row], cnt = g_indeg[row];
    for (int base = 0; base < cnt; base += 32) {
        int n = min(32, cnt - base);
        int idx_l = (base + l < cnt) ? g_csrsrc[start + base + l] : 0;
        for (int i = 0; i < n; i++) {
            int s = __shfl_sync(0xffffffffu, idx_l, i);
            float4 v = hw4[(size_t)s * 32 + l];
            acc.x += v.x; acc.y += v.y; acc.z += v.z; acc.w += v.w;
        }
    }
    float4 bv = ((const float4*)b1)[l];
    float4 xv;
    xv.x = selu_f(acc.x * dd + bv.x);
    xv.y = selu_f(acc.y * dd + bv.y);
    xv.z = selu_f(acc.z * dd + bv.z);
    xv.w = selu_f(acc.w * dd + bv.w);
    ((float4*)g_xd)[(size_t)row * 32 + l] = xv;
    *((float4*)&xds[wp][l * 4]) = xv;
    __syncwarp();

    float z = b2[l];
#pragma unroll
    for (int j = 0; j < HID; j += 4) {
        float4 xj = *(const float4*)&xds[wp][j];
        float4 wj = *(const float4*)&w2t[l * (HID + 4) + j];
        z += xj.x * wj.x + xj.y * wj.y + xj.z * wj.z + xj.w * wj.w;
    }
    float mx = z;
#pragma unroll
    for (int o = 16; o; o >>= 1) mx = fmaxf(mx, __shfl_xor_sync(0xffffffffu, mx, o));
    float ez = expf(z - mx);
    float sm = ez;
#pragma unroll
    for (int o = 16; o; o >>= 1) sm += __shfl_xor_sync(0xffffffffu, sm, o);
    float sv = ez / sm;
    s_out[(size_t)row * KC + l] = sv;
    g_s[(size_t)row * KC + l] = sv;
}

// per-graph reductions: out = s^T xd, ss = s^T s, ca = s^T deg, cs = s^T 1
// grid = 16 graphs * 16 chunks (128 nodes each), 512 threads
__global__ void __launch_bounds__(512) pool_k() {
    int g = blockIdx.x >> 4;
    int chunk = blockIdx.x & 15;
    int node0 = g * NN + chunk * 128;
    __shared__ float ssh[128 * 32];   // 16 KB
    __shared__ float dsh[128];
    int t = threadIdx.x;
    float4* ssh4 = (float4*)ssh;
    const float4* gs4 = (const float4*)g_s;
    for (int i = t; i < 128 * 8; i += 512) ssh4[i] = gs4[(size_t)node0 * 8 + i];
    if (t < 128) dsh[t] = (float)g_odeg[node0 + t];
    __syncthreads();

    int f = t & 127, kb = t >> 7;      // kb in 0..3 -> k = kb*8 .. kb*8+7
    int k1a = t >> 5;                  // 0..15
    int k2 = t & 31;
    float acc[8];
#pragma unroll
    for (int j = 0; j < 8; j++) acc[j] = 0.f;
    float ss0 = 0.f, ss1 = 0.f, csacc = 0.f, caacc = 0.f;

    for (int n = 0; n < 128; n++) {
        float xvv = g_xd[(size_t)(node0 + n) * HID + f];
        float4 s0 = ssh4[n * 8 + kb * 2];
        float4 s1 = ssh4[n * 8 + kb * 2 + 1];
        acc[0] += s0.x * xvv; acc[1] += s0.y * xvv; acc[2] += s0.z * xvv; acc[3] += s0.w * xvv;
        acc[4] += s1.x * xvv; acc[5] += s1.y * xvv; acc[6] += s1.z * xvv; acc[7] += s1.w * xvv;
        float sv2 = ssh[n * 32 + k2];
        ss0 += ssh[n * 32 + k1a] * sv2;
        ss1 += ssh[n * 32 + k1a + 16] * sv2;
        if (t < 32) { float sv = ssh[n * 32 + t]; csacc += sv; caacc += sv * dsh[n]; }
    }

    float* oa = g_outacc + (size_t)g * KC * HID;
#pragma unroll
    for (int j = 0; j < 8; j++) atomicAdd(&oa[(kb * 8 + j) * HID + f], acc[j]);
    atomicAdd(&g_ss[g * 1024 + t], ss0);          // cell t: (t>>5, t&31)
    atomicAdd(&g_ss[g * 1024 + t + 512], ss1);
    if (t < 32) {
        atomicAdd(&g_cs[g * 32 + t], csacc);
        atomicAdd(&g_ca[g * 32 + t], caacc);
    }
}

// trace(out_adj)[b] = sum over edges of dot(s[src], s[dst])
__global__ void __launch_bounds__(256) trace_k(const int* __restrict__ ei) {
    __shared__ float red[256];
    int base = blockIdx.x * 512;   // 512 edges per block; graph-aligned (EPG=32768)
    float accum = 0.f;
    const float4* s4 = (const float4*)g_s;
#pragma unroll
    for (int i = 0; i < 2; i++) {
        int e = base + i * 256 + threadIdx.x;
        int src = ei[e], dst = ei[EDG + e];
        float d = 0.f;
#pragma unroll
        for (int j = 0; j < 8; j++) {
            float4 a = s4[(size_t)src * 8 + j], b = s4[(size_t)dst * 8 + j];
            d += a.x * b.x + a.y * b.y + a.z * b.z + a.w * b.w;
        }
        accum += d;
    }
    red[threadIdx.x] = accum;
    __syncthreads();
    for (int o = 128; o; o >>= 1) {
        if (threadIdx.x < o) red[threadIdx.x] += red[threadIdx.x + o];
        __syncthreads();
    }
    if (threadIdx.x == 0) atomicAdd(&g_tr[base / EPG], red[0]);
}

// log_softmax(selu(outacc)) over F=128.  grid 512 (b,k) rows, 128 threads.
__global__ void __launch_bounds__(128) out_final_k(float* __restrict__ outp) {
    int r = blockIdx.x;
    int t = threadIdx.x;
    __shared__ float shm[4], shs[4];
    float y = selu_f(g_outacc[(size_t)r * HID + t]);
    float mx = y;
#pragma unroll
    for (int o = 16; o; o >>= 1) mx = fmaxf(mx, __shfl_xor_sync(0xffffffffu, mx, o));
    if ((t & 31) == 0) shm[t >> 5] = mx;
    __syncthreads();
    float mall = fmaxf(fmaxf(shm[0], shm[1]), fmaxf(shm[2], shm[3]));
    float e = expf(y - mall);
    float sm = e;
#pragma unroll
    for (int o = 16; o; o >>= 1) sm += __shfl_xor_sync(0xffffffffu, sm, o);
    if ((t & 31) == 0) shs[t >> 5] = sm;
    __syncthreads();
    float tot = shs[0] + shs[1] + shs[2] + shs[3];
    outp[(size_t)r * HID + t] = y - mall - logf(tot);
}

// scalar loss.  1 block, 16 warps (warp per graph).
__global__ void __launch_bounds__(512) loss_k(float* __restrict__ outp) {
    int w = threadIdx.x >> 5, l = threadIdx.x & 31;
    __shared__ float parts[16];
    // m = 0.5 * sum(out-degrees)
    float dsum = 0.f;
    for (int n = l; n < NN; n += 32) dsum += (float)g_odeg[w * NN + n];
#pragma unroll
    for (int o = 16; o; o >>= 1) dsum += __shfl_xor_sync(0xffffffffu, dsum, o);
    float m = 0.5f * dsum;

    // spectral
    float ca = g_ca[w * 32 + l];
    float cn = ca * ca;
#pragma unroll
    for (int o = 16; o; o >>= 1) cn += __shfl_xor_sync(0xffffffffu, cn, o);
    float norm_tr = cn / (2.f * m);
    float spec = -(g_tr[w] - norm_tr) / (2.f * m);

    // ortho: sqrt(2 - 2*tr(ss)/(||ss||_F * sqrt(K)))
    float sq = 0.f;
    for (int i = l; i < KC * KC; i += 32) { float v = g_ss[w * 1024 + i]; sq += v * v; }
#pragma unroll
    for (int o = 16; o; o >>= 1) sq += __shfl_xor_sync(0xffffffffu, sq, o);
    float fro = sqrtf(sq);
    float dtr = g_ss[w * 1024 + l * 33];   // diag element l
#pragma unroll
    for (int o = 16; o; o >>= 1) dtr += __shfl_xor_sync(0xffffffffu, dtr, o);
    float ortho = sqrtf(fmaxf(2.f - 2.f * dtr / (fro * sqrtf((float)KC)), 0.f));

    // cluster
    float cs = g_cs[w * 32 + l];
    float csn = cs * cs;
#pragma unroll
    for (int o = 16; o; o >>= 1) csn += __shfl_xor_sync(0xffffffffu, csn, o);
    float clus = sqrtf(csn) / (float)NN * sqrtf((float)KC) - 1.f;

    if (l == 0) parts[w] = spec + ortho + clus;
    __syncthreads();
    if (threadIdx.x == 0) {
        float tot = 0.f;
#pragma unroll
        for (int i = 0; i < 16; i++) tot += parts[i];
        outp[NGB * KC * HID] = tot / (float)NGB;   // outp[65536]
    }
}

// ---------------- launch ----------------
extern "C" void kernel_launch(void* const* d_in, const int* in_sizes, int n_in,
                              void* d_out, int out_size) {
    const float *x = 0, *gw = 0, *gb = 0, *gms = 0, *w1 = 0, *b1 = 0, *w2 = 0, *b2 = 0;
    const int *ei = 0;
    int n64 = 0;
    for (int i = 0; i < n_in; i++) {
        int sz = in_sizes[i];
        if (sz == NTT * CIN)       x = (const float*)d_in[i];
        else if (sz == 2 * EDG)    ei = (const int*)d_in[i];
        else if (sz == NTT)        { /* batch, unused (uniform graphs) */ }
        else if (sz == CIN) {
            if (n64 == 0) gw = (const float*)d_in[i];
            else if (n64 == 1) gb = (const float*)d_in[i];
            else gms = (const float*)d_in[i];
            n64++;
        }
        else if (sz == CIN * HID)  w1 = (const float*)d_in[i];
        else if (sz == HID)        b1 = (const float*)d_in[i];
        else if (sz == HID * KC)   w2 = (const float*)d_in[i];
        else if (sz == KC)         b2 = (const float*)d_in[i];
    }
    float* outp = (float*)d_out;
    float* s_out = outp + NGB * KC * HID + 1;   // s at offset 65537

    zero_k<<<256, 256>>>();
    gn_stats_k<<<NGB * 8, 512>>>(x);
    deg_hist_k<<<EDG / 256, 256>>>(ei);
    scan_k<<<1, 1024>>>();
    gn_gemm1_k<<<NTT / 16, 128>>>(x, gw, gb, gms, w1);
    csr_scatter_k<<<EDG / 256, 256>>>(ei);
    gxs_k<<<NTT / 8, 256>>>(b1, w2, b2, s_out);
    pool_k<<<NGB * 16, 512>>>();
    trace_k<<<EDG / 512, 256>>>(ei);
    out_final_k<<<NGB * KC, 128>>>(outp);
    loss_k<<<1, 512>>>(outp);
}

// round 3
// speedup vs baseline: 1.8674x; 1.3034x over previous
#include <cuda_runtime.h>
#include <math.h>

// Problem constants (fixed by the dataset)
#define NGB 16          // graphs
#define NN  2048        // nodes per graph
#define NTT 32768       // total nodes
#define CIN 64
#define HID 128
#define KC  32
#define EDG 524288      // total edges
#define EPG 32768       // edges per graph
#define GN_EPS 1e-5f
#define SELU_SCALE 1.0507009873554805f
#define SELU_ALPHA 1.6732632423543772f

// ---------------- scratch (device globals; no allocation allowed) ----------------
__device__ __align__(16) float g_sum[NGB * CIN];
__device__ __align__(16) float g_sumsq[NGB * CIN];
__device__ int   g_indeg[NTT];                 // in-degree (excl self loop)
__device__ int   g_odeg[NTT];                  // out-degree (adj degrees)
__device__ int   g_rowptr[NTT];                // CSR row start (by dst)
__device__ int   g_cursor[NTT];                // scatter cursors
__device__ int   g_csrsrc[EDG];                // CSR: src node per slot
__device__ int   g_bsum[128];                  // scan block sums
__device__ int   g_boff[128];                  // scan block offsets
__device__ __align__(16) float g_dinv[NTT];
__device__ __align__(16) float g_hw[NTT * HID];   // dinv * (graphnorm(x) @ w1)
__device__ __align__(16) float g_xd[NTT * HID];   // selu(agg+b1)
__device__ __align__(16) float g_s[NTT * KC];     // aligned copy of s
__device__ float g_tr[NGB];                       // trace(out_adj)
__device__ float g_ca[NGB * KC];
__device__ float g_cs[NGB * KC];
__device__ __align__(16) float g_ss[NGB * KC * KC];
__device__ __align__(16) float g_outacc[NGB * KC * HID];

__device__ __forceinline__ float selu_f(float v) {
    return v > 0.f ? SELU_SCALE * v : SELU_SCALE * SELU_ALPHA * (expf(v) - 1.f);
}

// ---------------- kernels ----------------

__global__ void zero_k() {
    int i = blockIdx.x * blockDim.x + threadIdx.x;
    int stride = gridDim.x * blockDim.x;
    for (int j = i; j < NTT; j += stride) { g_indeg[j] = 0; g_odeg[j] = 0; }
    for (int j = i; j < NGB * KC * HID; j += stride) g_outacc[j] = 0.f;
    for (int j = i; j < NGB * KC * KC; j += stride) g_ss[j] = 0.f;
    for (int j = i; j < NGB * CIN; j += stride) { g_sum[j] = 0.f; g_sumsq[j] = 0.f; }
    for (int j = i; j < NGB * KC; j += stride) { g_ca[j] = 0.f; g_cs[j] = 0.f; }
    for (int j = i; j < NGB; j += stride) g_tr[j] = 0.f;
}

// per-graph sum & sumsq per channel. grid = NGB*8 blocks of 512.
__global__ void __launch_bounds__(512) gn_stats_k(const float* __restrict__ x) {
    int g = blockIdx.x >> 3;
    int part = blockIdx.x & 7;           // 256 rows per part
    int t = threadIdx.x;
    int c = t & 63, rp = t >> 6;         // 8 row-phases
    float s = 0.f, q = 0.f;
    const float* xb = x + (size_t)g * NN * CIN;
    int r0 = part * 256;
    for (int r = r0 + rp; r < r0 + 256; r += 8) {
        float v = xb[r * CIN + c];
        s += v; q += v * v;
    }
    __shared__ float sh[2][8][64];
    sh[0][rp][c] = s; sh[1][rp][c] = q;
    __syncthreads();
    if (t < 64) {
        float ss = 0.f, qq = 0.f;
#pragma unroll
        for (int i = 0; i < 8; i++) { ss += sh[0][i][t]; qq += sh[1][i][t]; }
        atomicAdd(&g_sum[g * 64 + t], ss);
        atomicAdd(&g_sumsq[g * 64 + t], qq);
    }
}

__global__ void deg_hist_k(const int* __restrict__ ei) {
    int e = blockIdx.x * blockDim.x + threadIdx.x;
    if (e < EDG) {
        atomicAdd(&g_indeg[ei[EDG + e]], 1);   // dst in-degree
        atomicAdd(&g_odeg[ei[e]], 1);          // src out-degree (adj degrees)
    }
}

// ---- hierarchical exclusive scan of g_indeg (32768 = 128 blocks x 256) ----

// phase 1: per-block scan; local exclusive prefix -> g_rowptr (temp), block total -> g_bsum
__global__ void __launch_bounds__(256) scan1_k() {
    int b = blockIdx.x, t = threadIdx.x;
    int i = b * 256 + t;
    int v = g_indeg[i];
    int lane = t & 31, wp = t >> 5;
    int x = v;
#pragma unroll
    for (int o = 1; o < 32; o <<= 1) {
        int y = __shfl_up_sync(0xffffffffu, x, o);
        if (lane >= o) x += y;
    }
    __shared__ int ws[8];
    if (lane == 31) ws[wp] = x;
    __syncthreads();
    if (t == 0) {
        int run = 0;
#pragma unroll
        for (int w = 0; w < 8; w++) { int tmp = ws[w]; ws[w] = run; run += tmp; }
        g_bsum[b] = run;
    }
    __syncthreads();
    g_rowptr[i] = x - v + ws[wp];   // local exclusive prefix
}

// phase 2: scan the 128 block sums
__global__ void __launch_bounds__(128) scan2_k() {
    int t = threadIdx.x;
    __shared__ int sh[128];
    int v = g_bsum[t];
    sh[t] = v;
    __syncthreads();
    for (int o = 1; o < 128; o <<= 1) {
        int y = (t >= o) ? sh[t - o] : 0;
        __syncthreads();
        sh[t] += y;
        __syncthreads();
    }
    g_boff[t] = sh[t] - v;
}

// phase 3: finalize rowptr/cursor, compute dinv
__global__ void __launch_bounds__(256) scan3_k() {
    int b = blockIdx.x, t = threadIdx.x;
    int i = b * 256 + t;
    int rp = g_rowptr[i] + g_boff[b];
    g_rowptr[i] = rp;
    g_cursor[i] = rp;
    g_dinv[i] = rsqrtf((float)g_indeg[i] + 1.f);   // +1 self loop
}

// CSR scatter: slot = cursor[dst]++, csrsrc[slot] = src
__global__ void csr_scatter_k(const int* __restrict__ ei) {
    int e = blockIdx.x * blockDim.x + threadIdx.x;
    if (e < EDG) {
        int src = ei[e], dst = ei[EDG + e];
        int pos = atomicAdd(&g_cursor[dst], 1);
        g_csrsrc[pos] = src;
    }
}

// fused GraphNorm + GEMM1 (+ dinv scaling): g_hw = dinv * (graphnorm(x) @ w1)
// grid 512 blocks of 128 threads, grid-stride over 2048 tiles of 16 rows.
__global__ void __launch_bounds__(128) gn_gemm1_k(
    const float* __restrict__ x, const float* __restrict__ gw,
    const float* __restrict__ gb, const float* __restrict__ gms,
    const float* __restrict__ w1)
{
    __shared__ float w1t[HID * (CIN + 4)];   // ~34 KB, w1t[t][c] = w1[c][t]
    __shared__ float A[CIN], S[CIN], Bc[CIN];
    __shared__ float hsh[8][CIN];
    __shared__ float dvs[16];
    int t = threadIdx.x;
    for (int c = 0; c < CIN; c++)
        w1t[t * (CIN + 4) + c] = w1[c * HID + t];

    for (int tile = blockIdx.x; tile < NTT / 16; tile += 512) {
        int row0 = tile * 16;
        int g = row0 >> 11;
        __syncthreads();
        if (t < CIN) {
            float mean = g_sum[g * 64 + t] * (1.f / NN);
            float alpha = gms[t];
            float var = g_sumsq[g * 64 + t] * (1.f / NN) - (2.f * alpha - alpha * alpha) * mean * mean;
            S[t] = gw[t] * rsqrtf(var + GN_EPS);
            A[t] = alpha * mean;
            Bc[t] = gb[t];
        }
        if (t < 16) dvs[t] = g_dinv[row0 + t];
        __syncthreads();
        for (int p = 0; p < 2; p++) {
            int r0 = row0 + p * 8;
#pragma unroll
            for (int i = 0; i < 4; i++) {
                int idx = t + i * 128;
                int rr = idx >> 6, c = idx & 63;
                float v = x[(size_t)(r0 + rr) * CIN + c];
                hsh[rr][c] = (v - A[c]) * S[c] + Bc[c];
            }
            __syncthreads();
            float acc[8];
#pragma unroll
            for (int r = 0; r < 8; r++) acc[r] = 0.f;
#pragma unroll
            for (int c = 0; c < CIN; c += 4) {
                float4 w = *(const float4*)&w1t[t * (CIN + 4) + c];
#pragma unroll
                for (int r = 0; r < 8; r++) {
                    float4 h = *(const float4*)&hsh[r][c];
                    acc[r] += w.x * h.x + w.y * h.y + w.z * h.z + w.w * h.w;
                }
            }
#pragma unroll
            for (int r = 0; r < 8; r++)
                g_hw[(size_t)(r0 + r) * HID + t] = acc[r] * dvs[p * 8 + r];
            __syncthreads();
        }
    }
}

// fused CSR gather + SELU + softmax(xd @ w2 + b2).
// one warp per dst row; 1024 blocks x 8 warps, grid-stride (4 sweeps).
__global__ void __launch_bounds__(256) gxs_k(
    const float* __restrict__ b1, const float* __restrict__ w2,
    const float* __restrict__ b2, float* __restrict__ s_out)
{
    __shared__ float w2t[KC * (HID + 4)];   // ~17 KB, w2t[l][j] = w2[j][l]
    __shared__ float xds[8][HID];
    int t = threadIdx.x, wp = t >> 5, l = t & 31;
    for (int idx = t; idx < KC * HID; idx += 256) {
        int j = idx >> 5, ll = idx & 31;
        w2t[ll * (HID + 4) + j] = w2[idx];
    }
    __syncthreads();

    float4 bv = ((const float4*)b1)[l];
    float bz = b2[l];
    const float4* hw4 = (const float4*)g_hw;

    for (int row = blockIdx.x * 8 + wp; row < NTT; row += 8192) {
        float dd = g_dinv[row];
        float4 acc = hw4[(size_t)row * 32 + l];      // self-loop term p_d
        int start = g_rowptr[row], cnt = g_indeg[row];
        for (int base = 0; base < cnt; base += 32) {
            int n = min(32, cnt - base);
            int idx_l = (base + l < cnt) ? g_csrsrc[start + base + l] : 0;
            for (int i = 0; i < n; i++) {
                int s = __shfl_sync(0xffffffffu, idx_l, i);
                float4 v = hw4[(size_t)s * 32 + l];
                acc.x += v.x; acc.y += v.y; acc.z += v.z; acc.w += v.w;
            }
        }
        float4 xv;
        xv.x = selu_f(acc.x * dd + bv.x);
        xv.y = selu_f(acc.y * dd + bv.y);
        xv.z = selu_f(acc.z * dd + bv.z);
        xv.w = selu_f(acc.w * dd + bv.w);
        ((float4*)g_xd)[(size_t)row * 32 + l] = xv;
        *((float4*)&xds[wp][l * 4]) = xv;
        __syncwarp();

        float z = bz;
#pragma unroll
        for (int j = 0; j < HID; j += 4) {
            float4 xj = *(const float4*)&xds[wp][j];
            float4 wj = *(const float4*)&w2t[l * (HID + 4) + j];
            z += xj.x * wj.x + xj.y * wj.y + xj.z * wj.z + xj.w * wj.w;
        }
        float mx = z;
#pragma unroll
        for (int o = 16; o; o >>= 1) mx = fmaxf(mx, __shfl_xor_sync(0xffffffffu, mx, o));
        float ez = expf(z - mx);
        float sm = ez;
#pragma unroll
        for (int o = 16; o; o >>= 1) sm += __shfl_xor_sync(0xffffffffu, sm, o);
        float sv = ez / sm;
        s_out[(size_t)row * KC + l] = sv;
        g_s[(size_t)row * KC + l] = sv;
        __syncwarp();
    }
}

// per-graph reductions: out = s^T xd, ss = s^T s, ca = s^T deg, cs = s^T 1
// grid = 16 graphs * 16 chunks (128 nodes each), 512 threads
__global__ void __launch_bounds__(512) pool_k() {
    int g = blockIdx.x >> 4;
    int chunk = blockIdx.x & 15;
    int node0 = g * NN + chunk * 128;
    __shared__ float ssh[128 * 32];   // 16 KB
    __shared__ float dsh[128];
    int t = threadIdx.x;
    float4* ssh4 = (float4*)ssh;
    const float4* gs4 = (const float4*)g_s;
    for (int i = t; i < 128 * 8; i += 512) ssh4[i] = gs4[(size_t)node0 * 8 + i];
    if (t < 128) dsh[t] = (float)g_odeg[node0 + t];
    __syncthreads();

    int f = t & 127, kb = t >> 7;      // kb in 0..3 -> k = kb*8 .. kb*8+7
    int k1a = t >> 5;                  // 0..15
    int k2 = t & 31;
    float acc[8];
#pragma unroll
    for (int j = 0; j < 8; j++) acc[j] = 0.f;
    float ss0 = 0.f, ss1 = 0.f, csacc = 0.f, caacc = 0.f;

    for (int n = 0; n < 128; n++) {
        float xvv = g_xd[(size_t)(node0 + n) * HID + f];
        float4 s0 = ssh4[n * 8 + kb * 2];
        float4 s1 = ssh4[n * 8 + kb * 2 + 1];
        acc[0] += s0.x * xvv; acc[1] += s0.y * xvv; acc[2] += s0.z * xvv; acc[3] += s0.w * xvv;
        acc[4] += s1.x * xvv; acc[5] += s1.y * xvv; acc[6] += s1.z * xvv; acc[7] += s1.w * xvv;
        float sv2 = ssh[n * 32 + k2];
        ss0 += ssh[n * 32 + k1a] * sv2;
        ss1 += ssh[n * 32 + k1a + 16] * sv2;
        if (t < 32) { float sv = ssh[n * 32 + t]; csacc += sv; caacc += sv * dsh[n]; }
    }

    float* oa = g_outacc + (size_t)g * KC * HID;
#pragma unroll
    for (int j = 0; j < 8; j++) atomicAdd(&oa[(kb * 8 + j) * HID + f], acc[j]);
    atomicAdd(&g_ss[g * 1024 + t], ss0);          // cell t: (t>>5, t&31)
    atomicAdd(&g_ss[g * 1024 + t + 512], ss1);
    if (t < 32) {
        atomicAdd(&g_cs[g * 32 + t], csacc);
        atomicAdd(&g_ca[g * 32 + t], caacc);
    }
}

// trace(out_adj)[b] = sum over edges of dot(s[src], s[dst])
__global__ void __launch_bounds__(256) trace_k(const int* __restrict__ ei) {
    __shared__ float red[256];
    int base = blockIdx.x * 512;   // 512 edges per block; graph-aligned (EPG=32768)
    float accum = 0.f;
    const float4* s4 = (const float4*)g_s;
#pragma unroll
    for (int i = 0; i < 2; i++) {
        int e = base + i * 256 + threadIdx.x;
        int src = ei[e], dst = ei[EDG + e];
        float d = 0.f;
#pragma unroll
        for (int j = 0; j < 8; j++) {
            float4 a = s4[(size_t)src * 8 + j], b = s4[(size_t)dst * 8 + j];
            d += a.x * b.x + a.y * b.y + a.z * b.z + a.w * b.w;
        }
        accum += d;
    }
    red[threadIdx.x] = accum;
    __syncthreads();
    for (int o = 128; o; o >>= 1) {
        if (threadIdx.x < o) red[threadIdx.x] += red[threadIdx.x + o];
        __syncthreads();
    }
    if (threadIdx.x == 0) atomicAdd(&g_tr[base / EPG], red[0]);
}

// log_softmax(selu(outacc)) over F=128.  grid 512 (b,k) rows, 128 threads.
__global__ void __launch_bounds__(128) out_final_k(float* __restrict__ outp) {
    int r = blockIdx.x;
    int t = threadIdx.x;
    __shared__ float shm[4], shs[4];
    float y = selu_f(g_outacc[(size_t)r * HID + t]);
    float mx = y;
#pragma unroll
    for (int o = 16; o; o >>= 1) mx = fmaxf(mx, __shfl_xor_sync(0xffffffffu, mx, o));
    if ((t & 31) == 0) shm[t >> 5] = mx;
    __syncthreads();
    float mall = fmaxf(fmaxf(shm[0], shm[1]), fmaxf(shm[2], shm[3]));
    float e = expf(y - mall);
    float sm = e;
#pragma unroll
    for (int o = 16; o; o >>= 1) sm += __shfl_xor_sync(0xffffffffu, sm, o);
    if ((t & 31) == 0) shs[t >> 5] = sm;
    __syncthreads();
    float tot = shs[0] + shs[1] + shs[2] + shs[3];
    outp[(size_t)r * HID + t] = y - mall - logf(tot);
}

// scalar loss.  1 block, 16 warps (warp per graph).
__global__ void __launch_bounds__(512) loss_k(float* __restrict__ outp) {
    int w = threadIdx.x >> 5, l = threadIdx.x & 31;
    __shared__ float parts[16];
    // m = 0.5 * sum(out-degrees)
    float dsum = 0.f;
    for (int n = l; n < NN; n += 32) dsum += (float)g_odeg[w * NN + n];
#pragma unroll
    for (int o = 16; o; o >>= 1) dsum += __shfl_xor_sync(0xffffffffu, dsum, o);
    float m = 0.5f * dsum;

    // spectral
    float ca = g_ca[w * 32 + l];
    float cn = ca * ca;
#pragma unroll
    for (int o = 16; o; o >>= 1) cn += __shfl_xor_sync(0xffffffffu, cn, o);
    float norm_tr = cn / (2.f * m);
    float spec = -(g_tr[w] - norm_tr) / (2.f * m);

    // ortho: sqrt(2 - 2*tr(ss)/(||ss||_F * sqrt(K)))
    float sq = 0.f;
    for (int i = l; i < KC * KC; i += 32) { float v = g_ss[w * 1024 + i]; sq += v * v; }
#pragma unroll
    for (int o = 16; o; o >>= 1) sq += __shfl_xor_sync(0xffffffffu, sq, o);
    float fro = sqrtf(sq);
    float dtr = g_ss[w * 1024 + l * 33];   // diag element l
#pragma unroll
    for (int o = 16; o; o >>= 1) dtr += __shfl_xor_sync(0xffffffffu, dtr, o);
    float ortho = sqrtf(fmaxf(2.f - 2.f * dtr / (fro * sqrtf((float)KC)), 0.f));

    // cluster
    float cs = g_cs[w * 32 + l];
    float csn = cs * cs;
#pragma unroll
    for (int o = 16; o; o >>= 1) csn += __shfl_xor_sync(0xffffffffu, csn, o);
    float clus = sqrtf(csn) / (float)NN * sqrtf((float)KC) - 1.f;

    if (l == 0) parts[w] = spec + ortho + clus;
    __syncthreads();
    if (threadIdx.x == 0) {
        float tot = 0.f;
#pragma unroll
        for (int i = 0; i < 16; i++) tot += parts[i];
        outp[NGB * KC * HID] = tot / (float)NGB;   // outp[65536]
    }
}

// ---------------- launch ----------------
extern "C" void kernel_launch(void* const* d_in, const int* in_sizes, int n_in,
                              void* d_out, int out_size) {
    const float *x = 0, *gw = 0, *gb = 0, *gms = 0, *w1 = 0, *b1 = 0, *w2 = 0, *b2 = 0;
    const int *ei = 0;
    int n64 = 0;
    for (int i = 0; i < n_in; i++) {
        int sz = in_sizes[i];
        if (sz == NTT * CIN)       x = (const float*)d_in[i];
        else if (sz == 2 * EDG)    ei = (const int*)d_in[i];
        else if (sz == NTT)        { /* batch, unused (uniform graphs) */ }
        else if (sz == CIN) {
            if (n64 == 0) gw = (const float*)d_in[i];
            else if (n64 == 1) gb = (const float*)d_in[i];
            else gms = (const float*)d_in[i];
            n64++;
        }
        else if (sz == CIN * HID)  w1 = (const float*)d_in[i];
        else if (sz == HID)        b1 = (const float*)d_in[i];
        else if (sz == HID * KC)   w2 = (const float*)d_in[i];
        else if (sz == KC)         b2 = (const float*)d_in[i];
    }
    float* outp = (float*)d_out;
    float* s_out = outp + NGB * KC * HID + 1;   // s at offset 65537

    zero_k<<<256, 256>>>();
    gn_stats_k<<<NGB * 8, 512>>>(x);
    deg_hist_k<<<EDG / 256, 256>>>(ei);
    scan1_k<<<128, 256>>>();
    scan2_k<<<1, 128>>>();
    scan3_k<<<128, 256>>>();
    gn_gemm1_k<<<512, 128>>>(x, gw, gb, gms, w1);
    csr_scatter_k<<<EDG / 256, 256>>>(ei);
    gxs_k<<<1024, 256>>>(b1, w2, b2, s_out);
    pool_k<<<NGB * 16, 512>>>();
    trace_k<<<EDG / 512, 256>>>(ei);
    out_final_k<<<NGB * KC, 128>>>(outp);
    loss_k<<<1, 512>>>(outp);
}